// round 4
// baseline (speedup 1.0000x reference)
#include <cuda_runtime.h>

#define Bq 8
#define Nq 8192
#define Cq 128
#define Mq 2048
#define Kq 32

// scratch for knn indices (allocation-free: device global)
__device__ int g_knn[Bq * Mq * Kq];

// ---------------------------------------------------------------------------
// FPS: one block per batch. Coords cached in SMEM as float4, per-thread dist
// in registers (16 points/thread, stride-512 so LDS.128 is conflict-free).
// Squared-distance domain (monotone-equivalent to reference's L2 norm).
// Verified bit-exact vs reference in R2/R3 (output 0 rel_err = 0).
// ---------------------------------------------------------------------------
__global__ void __launch_bounds__(512, 1) fps_kernel(
    const float* __restrict__ coords, float* __restrict__ out_coords)
{
    extern __shared__ float4 sp[];     // Nq float4 = 128 KB
    __shared__ float s_val[16];
    __shared__ int   s_idx[16];
    __shared__ int   s_cur;

    const int b   = blockIdx.x;
    const int tid = threadIdx.x;
    const float* cb = coords + (size_t)b * Nq * 3;

    for (int j = tid; j < Nq; j += 512)
        sp[j] = make_float4(cb[3 * j], cb[3 * j + 1], cb[3 * j + 2], 0.0f);
    __syncthreads();

    float dist[16];
#pragma unroll
    for (int i = 0; i < 16; ++i) dist[i] = 3.0e38f;

    int cur = 0;  // first sampled point is index 0 (reference init)
    float* ob = out_coords + (size_t)b * Mq * 3;

    for (int step = 0; step < Mq; ++step) {
        const float4 c = sp[cur];
        if (tid == 0) {
            ob[3 * step + 0] = c.x;
            ob[3 * step + 1] = c.y;
            ob[3 * step + 2] = c.z;
        }

        float bv = -1.0f;
        int   bi = 0;
#pragma unroll
        for (int i = 0; i < 16; ++i) {
            const int p = i * 512 + tid;
            const float4 q = sp[p];
            const float dx = q.x - c.x, dy = q.y - c.y, dz = q.z - c.z;
            // plain mul/add (no FMA contraction) to track XLA's square+sum
            const float d2 = __fadd_rn(
                __fadd_rn(__fmul_rn(dx, dx), __fmul_rn(dy, dy)),
                __fmul_rn(dz, dz));
            const float nd = fminf(dist[i], d2);
            dist[i] = nd;
            // ascending p within thread + strict '>' keeps lowest index on ties
            if (nd > bv) { bv = nd; bi = p; }
        }

        // warp argmax reduce (value desc, index asc on ties)
#pragma unroll
        for (int o = 16; o > 0; o >>= 1) {
            const float ov = __shfl_down_sync(0xffffffffu, bv, o);
            const int   oi = __shfl_down_sync(0xffffffffu, bi, o);
            if (ov > bv || (ov == bv && oi < bi)) { bv = ov; bi = oi; }
        }
        const int w = tid >> 5, l = tid & 31;
        if (l == 0) { s_val[w] = bv; s_idx[w] = bi; }
        __syncthreads();
        if (w == 0) {
            bv = (l < 16) ? s_val[l] : -3.0e38f;
            bi = (l < 16) ? s_idx[l] : 0x7fffffff;
#pragma unroll
            for (int o = 8; o > 0; o >>= 1) {
                const float ov = __shfl_down_sync(0xffffffffu, bv, o);
                const int   oi = __shfl_down_sync(0xffffffffu, bi, o);
                if (ov > bv || (ov == bv && oi < bi)) { bv = ov; bi = oi; }
            }
            if (l == 0) s_cur = bi;
        }
        __syncthreads();
        cur = s_cur;
    }
}

// ---------------------------------------------------------------------------
// kNN: thread-per-center, 128 threads/block, 16 blocks per batch (128 CTAs).
// Reference numerics (fp32 everywhere):
//   d2 = (c2 + p2) - 2*dot,  dot = fp32 fma chain (== cublas SGEMM K-loop,
//   since fma(a,b,0) rounds once), c2/p2 = ((x*x + y*y) + z*z).
// Streaming top-32 with STABLE top_k semantics:
//   - insertion: strict '<' (equal-valued candidate has higher stream index
//     than all buffer entries -> buffer wins, matching lower-index-first)
//   - eviction: among equal max values evict the HIGHEST index, so
//     lowest-index duplicates survive (this was the R2 single-flip bug)
// ---------------------------------------------------------------------------
__global__ void __launch_bounds__(128, 1) knn_kernel(
    const float* __restrict__ coords, const float* __restrict__ out_coords)
{
    extern __shared__ float4 sp[];     // Nq float4 = 128 KB
    const int b   = blockIdx.y;
    const int tid = threadIdx.x;
    const float* cb = coords + (size_t)b * Nq * 3;

    for (int j = tid; j < Nq; j += 128) {
        const float x = cb[3 * j], y = cb[3 * j + 1], z = cb[3 * j + 2];
        const float p2 = __fadd_rn(
            __fadd_rn(__fmul_rn(x, x), __fmul_rn(y, y)), __fmul_rn(z, z));
        sp[j] = make_float4(x, y, z, p2);
    }
    __syncthreads();

    const int m = blockIdx.x * 128 + tid;
    const float* cc = out_coords + ((size_t)b * Mq + m) * 3;
    const float cx = cc[0], cy = cc[1], cz = cc[2];
    const float c2 = __fadd_rn(
        __fadd_rn(__fmul_rn(cx, cx), __fmul_rn(cy, cy)), __fmul_rn(cz, cz));

    float bd[Kq];
    int   bix[Kq];
#pragma unroll
    for (int s = 0; s < Kq; ++s) { bd[s] = 3.0e38f; bix[s] = 0x7fffffff; }
    float wv = 3.0e38f;   // current worst (max) kept distance
    int   wp = 0;         // its slot (evict target)

#pragma unroll 4
    for (int j = 0; j < Nq; ++j) {
        const float4 q = sp[j];
        const float dot = fmaf(cz, q.z, fmaf(cy, q.y, __fmul_rn(cx, q.x)));
        const float d2 = __fsub_rn(__fadd_rn(c2, q.w), __fmul_rn(2.0f, dot));
        if (d2 < wv) {
            bd[wp] = d2; bix[wp] = j;
            // rescan for next evict target: max value; ties -> max index,
            // so lowest-index duplicates are kept (stable top_k semantics)
            float nv = -3.0e38f; int ni = -1; int np = 0;
#pragma unroll
            for (int s = 0; s < Kq; ++s) {
                const bool take = (bd[s] > nv) || (bd[s] == nv && bix[s] > ni);
                if (take) { nv = bd[s]; ni = bix[s]; np = s; }
            }
            wv = nv; wp = np;
        }
    }

    int* ko = g_knn + ((size_t)b * Mq + m) * Kq;
#pragma unroll
    for (int s = 0; s < Kq; ++s) ko[s] = bix[s];
}

// ---------------------------------------------------------------------------
// Aggregation: one block per (b, m), one thread per channel. Coalesced
// gathers of 32 feature rows; mean = sum * (1/32).
// ---------------------------------------------------------------------------
__global__ void __launch_bounds__(128, 1) agg_kernel(
    const float* __restrict__ feats, float* __restrict__ out_feats)
{
    const int bm  = blockIdx.x;
    const int b   = bm >> 11;          // / Mq
    const int tid = threadIdx.x;       // channel
    __shared__ int nb[Kq];
    if (tid < Kq) nb[tid] = g_knn[(size_t)bm * Kq + tid];
    __syncthreads();

    const float* fb = feats + (size_t)b * Nq * Cq;
    float acc = 0.0f;
#pragma unroll
    for (int s = 0; s < Kq; ++s)
        acc += fb[(size_t)nb[s] * Cq + tid];
    out_feats[(size_t)bm * Cq + tid] = acc * 0.03125f;
}

// ---------------------------------------------------------------------------
extern "C" void kernel_launch(void* const* d_in, const int* in_sizes, int n_in,
                              void* d_out, int out_size)
{
    const float* coords = (const float*)d_in[0];  // (8, 8192, 3) f32
    const float* feats  = (const float*)d_in[1];  // (8, 8192, 128) f32
    float* out        = (float*)d_out;
    float* out_coords = out;                       // (8, 2048, 3)
    float* out_feats  = out + (size_t)Bq * Mq * 3; // (8, 2048, 128)

    // 128 KB dynamic smem opt-in (idempotent; not a stream op, capture-safe)
    cudaFuncSetAttribute(fps_kernel, cudaFuncAttributeMaxDynamicSharedMemorySize,
                         Nq * (int)sizeof(float4));
    cudaFuncSetAttribute(knn_kernel, cudaFuncAttributeMaxDynamicSharedMemorySize,
                         Nq * (int)sizeof(float4));

    fps_kernel<<<Bq, 512, Nq * sizeof(float4)>>>(coords, out_coords);
    knn_kernel<<<dim3(Mq / 128, Bq), 128, Nq * sizeof(float4)>>>(coords, out_coords);
    agg_kernel<<<Bq * Mq, 128>>>(feats, out_feats);
}

// round 5
// speedup vs baseline: 1.1670x; 1.1670x over previous
#include <cuda_runtime.h>

#define Bq 8
#define Nq 8192
#define Cq 128
#define Mq 2048
#define Kq 32

typedef unsigned long long u64p;

// scratch for knn indices (allocation-free: device global)
__device__ int g_knn[Bq * Mq * Kq];

// ---- packed f32x2 helpers (per-lane rounding identical to scalar RN ops) ----
#define PK2(d, lo, hi)                                                      \
    asm("mov.b64 %0, {%1, %2};" : "=l"(d)                                   \
        : "r"(__float_as_uint(lo)), "r"(__float_as_uint(hi)))
#define UPK2(lo, hi, s)                                                     \
    do { unsigned _a, _b;                                                   \
         asm("mov.b64 {%0, %1}, %2;" : "=r"(_a), "=r"(_b) : "l"(s));        \
         (lo) = __uint_as_float(_a); (hi) = __uint_as_float(_b); } while (0)
#define ADD2(d, a, b) asm("add.rn.f32x2 %0, %1, %2;" : "=l"(d) : "l"(a), "l"(b))
#define MUL2(d, a, b) asm("mul.rn.f32x2 %0, %1, %2;" : "=l"(d) : "l"(a), "l"(b))
#define FMA2(d, a, b, c)                                                    \
    asm("fma.rn.f32x2 %0, %1, %2, %3;" : "=l"(d) : "l"(a), "l"(b), "l"(c))

// ---------------------------------------------------------------------------
// FPS: one block per batch, 512 threads, 16 points/thread held in REGISTERS
// as packed f32x2 pairs. Hot loop: 8 packed fma-pipe ops per point-pair,
// no shared-memory traffic (centroid is a single broadcast LDS per step).
// Bit-exact vs the R4-passing version:
//   dx = q.x + (-c.x) == q.x - c.x (IEEE), mul/add .rn per lane == scalar,
//   fminf dist update identical, argmax = value-max + descending equality
//   scan (keeps lowest index on ties, == ascending strict-'>' tracking).
// ---------------------------------------------------------------------------
__global__ void __launch_bounds__(512, 1) fps_kernel(
    const float* __restrict__ coords, float* __restrict__ out_coords)
{
    extern __shared__ float4 sp[];     // Nq float4 = 128 KB (centroid fetch)
    __shared__ float s_val[16];
    __shared__ int   s_idx[16];
    __shared__ int   s_cur;

    const int b   = blockIdx.x;
    const int tid = threadIdx.x;
    const float* cb = coords + (size_t)b * Nq * 3;

    for (int j = tid; j < Nq; j += 512)
        sp[j] = make_float4(cb[3 * j], cb[3 * j + 1], cb[3 * j + 2], 0.0f);
    __syncthreads();

    // pack 16 points (pair k = points 2k*512+tid, (2k+1)*512+tid) into regs
    u64p px[8], py[8], pz[8];
    float dist[16];
#pragma unroll
    for (int k = 0; k < 8; ++k) {
        const float4 a = sp[(2 * k) * 512 + tid];
        const float4 c = sp[(2 * k + 1) * 512 + tid];
        PK2(px[k], a.x, c.x);
        PK2(py[k], a.y, c.y);
        PK2(pz[k], a.z, c.z);
        dist[2 * k] = 3.0e38f; dist[2 * k + 1] = 3.0e38f;
    }

    int cur = 0;  // first sampled point is index 0 (reference init)
    float* ob = out_coords + (size_t)b * Mq * 3;

    for (int step = 0; step < Mq; ++step) {
        const float4 c = sp[cur];
        if (tid == 0) {
            ob[3 * step + 0] = c.x;
            ob[3 * step + 1] = c.y;
            ob[3 * step + 2] = c.z;
        }
        u64p ncx, ncy, ncz;
        PK2(ncx, -c.x, -c.x);
        PK2(ncy, -c.y, -c.y);
        PK2(ncz, -c.z, -c.z);

        float bv = -1.0f;
#pragma unroll
        for (int k = 0; k < 8; ++k) {
            u64p dx, dy, dz, xx, yy, zz, ss, dd;
            ADD2(dx, px[k], ncx);
            ADD2(dy, py[k], ncy);
            ADD2(dz, pz[k], ncz);
            MUL2(xx, dx, dx);
            MUL2(yy, dy, dy);
            MUL2(zz, dz, dz);
            ADD2(ss, xx, yy);
            ADD2(dd, ss, zz);
            float d0, d1; UPK2(d0, d1, dd);
            const float n0 = fminf(dist[2 * k], d0);
            const float n1 = fminf(dist[2 * k + 1], d1);
            dist[2 * k] = n0; dist[2 * k + 1] = n1;
            bv = fmaxf(bv, fmaxf(n0, n1));
        }
        // recover lowest point-index holding the per-thread max
        int bi = 0;
#pragma unroll
        for (int i = 15; i >= 0; --i)
            if (dist[i] == bv) bi = i * 512 + tid;

        // warp argmax reduce (value desc, index asc on ties)
#pragma unroll
        for (int o = 16; o > 0; o >>= 1) {
            const float ov = __shfl_down_sync(0xffffffffu, bv, o);
            const int   oi = __shfl_down_sync(0xffffffffu, bi, o);
            if (ov > bv || (ov == bv && oi < bi)) { bv = ov; bi = oi; }
        }
        const int w = tid >> 5, l = tid & 31;
        if (l == 0) { s_val[w] = bv; s_idx[w] = bi; }
        __syncthreads();
        if (w == 0) {
            bv = (l < 16) ? s_val[l] : -3.0e38f;
            bi = (l < 16) ? s_idx[l] : 0x7fffffff;
#pragma unroll
            for (int o = 8; o > 0; o >>= 1) {
                const float ov = __shfl_down_sync(0xffffffffu, bv, o);
                const int   oi = __shfl_down_sync(0xffffffffu, bi, o);
                if (ov > bv || (ov == bv && oi < bi)) { bv = ov; bi = oi; }
            }
            if (l == 0) s_cur = bi;
        }
        __syncthreads();
        cur = s_cur;
    }
}

// ---------------------------------------------------------------------------
// kNN: thread-per-center, 128 threads/block, 16 blocks/batch (128 CTAs).
// SMEM: SoA packed pairs (x,y,z,p2) -> all lanes of a warp read the same
// address each iteration (64-bit broadcast, conflict-free).
// Distance (bit-identical to R4-passing version):
//   dot = fma(z,cz, fma(y,cy, mul(x,cx)))        [per lane, packed f32x2]
//   d2  = fma(dot, -2, (c2 + p2))                 [2*dot exact -> same bits
//                                                  as (c2+p2) - 2*dot]
// Streaming top-32 insert/evict logic kept verbatim from the passing R4.
// ---------------------------------------------------------------------------
__global__ void __launch_bounds__(128, 1) knn_kernel(
    const float* __restrict__ coords, const float* __restrict__ out_coords)
{
    extern __shared__ u64p sm[];       // 4 arrays x 4096 u64 = 128 KB
    u64p* sux = sm;
    u64p* suy = sm + 4096;
    u64p* suz = sm + 8192;
    u64p* sp2 = sm + 12288;

    const int b   = blockIdx.y;
    const int tid = threadIdx.x;
    const float* cb = coords + (size_t)b * Nq * 3;

    for (int jp = tid; jp < 4096; jp += 128) {
        const int j0 = 2 * jp, j1 = j0 + 1;
        const float x0 = cb[3 * j0], y0 = cb[3 * j0 + 1], z0 = cb[3 * j0 + 2];
        const float x1 = cb[3 * j1], y1 = cb[3 * j1 + 1], z1 = cb[3 * j1 + 2];
        const float p20 = __fadd_rn(
            __fadd_rn(__fmul_rn(x0, x0), __fmul_rn(y0, y0)), __fmul_rn(z0, z0));
        const float p21 = __fadd_rn(
            __fadd_rn(__fmul_rn(x1, x1), __fmul_rn(y1, y1)), __fmul_rn(z1, z1));
        PK2(sux[jp], x0, x1);
        PK2(suy[jp], y0, y1);
        PK2(suz[jp], z0, z1);
        PK2(sp2[jp], p20, p21);
    }
    __syncthreads();

    const int m = blockIdx.x * 128 + tid;
    const float* cc = out_coords + ((size_t)b * Mq + m) * 3;
    const float cx = cc[0], cy = cc[1], cz = cc[2];
    const float c2 = __fadd_rn(
        __fadd_rn(__fmul_rn(cx, cx), __fmul_rn(cy, cy)), __fmul_rn(cz, cz));
    u64p vcx, vcy, vcz, vc2, vn2;
    PK2(vcx, cx, cx);
    PK2(vcy, cy, cy);
    PK2(vcz, cz, cz);
    PK2(vc2, c2, c2);
    PK2(vn2, -2.0f, -2.0f);

    float bd[Kq];
    int   bix[Kq];
#pragma unroll
    for (int s = 0; s < Kq; ++s) { bd[s] = 3.0e38f; bix[s] = 0x7fffffff; }
    float wv = 3.0e38f;   // current worst (max) kept distance
    int   wp = 0;         // its slot (evict target)

    // stable top_k insert (verbatim semantics from the passing R4 kernel):
    // insertion strict '<'; eviction: max value, ties -> max index
#define KNN_INSERT(DV, JV)                                                  \
    {                                                                       \
        bd[wp] = (DV); bix[wp] = (JV);                                      \
        float nv = -3.0e38f; int ni = -1; int np = 0;                       \
        _Pragma("unroll")                                                   \
        for (int s = 0; s < Kq; ++s) {                                      \
            const bool take = (bd[s] > nv) || (bd[s] == nv && bix[s] > ni); \
            if (take) { nv = bd[s]; ni = bix[s]; np = s; }                  \
        }                                                                   \
        wv = nv; wp = np;                                                   \
    }

#pragma unroll 4
    for (int jp = 0; jp < 4096; ++jp) {
        u64p t, dotv, s2, d2v;
        MUL2(t, sux[jp], vcx);
        FMA2(t, suy[jp], vcy, t);
        FMA2(dotv, suz[jp], vcz, t);
        ADD2(s2, vc2, sp2[jp]);
        FMA2(d2v, dotv, vn2, s2);
        float d0, d1; UPK2(d0, d1, d2v);
        if (d0 < wv) KNN_INSERT(d0, 2 * jp)
        if (d1 < wv) KNN_INSERT(d1, 2 * jp + 1)
    }
#undef KNN_INSERT

    int* ko = g_knn + ((size_t)b * Mq + m) * Kq;
#pragma unroll
    for (int s = 0; s < Kq; ++s) ko[s] = bix[s];
}

// ---------------------------------------------------------------------------
// Aggregation: 4 centers per 128-thread block; each thread owns 4 channels
// (float4). Per-channel adds in ascending neighbor order (same as before).
// ---------------------------------------------------------------------------
__global__ void __launch_bounds__(128, 1) agg_kernel(
    const float* __restrict__ feats, float* __restrict__ out_feats)
{
    const int slot = threadIdx.x >> 5;   // center slot in block (0..3)
    const int lane = threadIdx.x & 31;   // channel quad (0..31) -> 128 ch
    const int bm   = blockIdx.x * 4 + slot;
    const int b    = bm >> 11;           // / Mq

    __shared__ int nb[4][Kq];
    nb[slot][lane] = g_knn[(size_t)bm * Kq + lane];
    __syncwarp();

    const float4* fb = (const float4*)(feats + (size_t)b * Nq * Cq);
    float ax = 0.f, ay = 0.f, az = 0.f, aw = 0.f;
#pragma unroll
    for (int s = 0; s < Kq; ++s) {
        const float4 v = fb[(size_t)nb[slot][s] * 32 + lane];
        ax += v.x; ay += v.y; az += v.z; aw += v.w;
    }
    float4 r;
    r.x = ax * 0.03125f; r.y = ay * 0.03125f;
    r.z = az * 0.03125f; r.w = aw * 0.03125f;
    ((float4*)out_feats)[(size_t)bm * 32 + lane] = r;
}

// ---------------------------------------------------------------------------
extern "C" void kernel_launch(void* const* d_in, const int* in_sizes, int n_in,
                              void* d_out, int out_size)
{
    const float* coords = (const float*)d_in[0];  // (8, 8192, 3) f32
    const float* feats  = (const float*)d_in[1];  // (8, 8192, 128) f32
    float* out        = (float*)d_out;
    float* out_coords = out;                       // (8, 2048, 3)
    float* out_feats  = out + (size_t)Bq * Mq * 3; // (8, 2048, 128)

    // 128 KB dynamic smem opt-in (idempotent; capture-safe)
    cudaFuncSetAttribute(fps_kernel, cudaFuncAttributeMaxDynamicSharedMemorySize,
                         Nq * (int)sizeof(float4));
    cudaFuncSetAttribute(knn_kernel, cudaFuncAttributeMaxDynamicSharedMemorySize,
                         Nq * (int)sizeof(float4));

    fps_kernel<<<Bq, 512, Nq * sizeof(float4)>>>(coords, out_coords);
    knn_kernel<<<dim3(Mq / 128, Bq), 128, Nq * sizeof(float4)>>>(coords, out_coords);
    agg_kernel<<<Bq * Mq / 4, 128>>>(feats, out_feats);
}

// round 7
// speedup vs baseline: 1.8525x; 1.5874x over previous
#include <cuda_runtime.h>

#define Bq 8
#define Nq 8192
#define Cq 128
#define Mq 2048
#define Kq 32

typedef unsigned long long u64p;

// scratch for knn indices (allocation-free: device global)
__device__ int g_knn[Bq * Mq * Kq];

// ---- packed f32x2 helpers (per-lane rounding identical to scalar RN ops) ----
#define PK2(d, lo, hi)                                                      \
    asm("mov.b64 %0, {%1, %2};" : "=l"(d)                                   \
        : "r"(__float_as_uint(lo)), "r"(__float_as_uint(hi)))
#define UPK2(lo, hi, s)                                                     \
    do { unsigned _a, _b;                                                   \
         asm("mov.b64 {%0, %1}, %2;" : "=r"(_a), "=r"(_b) : "l"(s));        \
         (lo) = __uint_as_float(_a); (hi) = __uint_as_float(_b); } while (0)
#define ADD2(d, a, b) asm("add.rn.f32x2 %0, %1, %2;" : "=l"(d) : "l"(a), "l"(b))
#define MUL2(d, a, b) asm("mul.rn.f32x2 %0, %1, %2;" : "=l"(d) : "l"(a), "l"(b))
#define FMA2(d, a, b, c)                                                    \
    asm("fma.rn.f32x2 %0, %1, %2, %3;" : "=l"(d) : "l"(a), "l"(b), "l"(c))

__device__ __forceinline__ unsigned redux_max_u32(unsigned v) {
    unsigned r;
    asm("redux.sync.max.u32 %0, %1, 0xffffffff;" : "=r"(r) : "r"(v));
    return r;
}
__device__ __forceinline__ unsigned redux_min_u32(unsigned v) {
    unsigned r;
    asm("redux.sync.min.u32 %0, %1, 0xffffffff;" : "=r"(r) : "r"(v));
    return r;
}

// ---------------------------------------------------------------------------
// FPS: one block per batch, 512 threads, 16 points/thread in registers as
// packed f32x2 pairs. Distance math bit-identical to the passing R4/R5
// kernels. Argmax: warp redux.max on dist bits + redux.min on candidate
// index; stage2 reduces the 16 per-warp candidates redundantly in every
// warp -> ONE barrier per step (double-buffered staging).
// ---------------------------------------------------------------------------
__global__ void __launch_bounds__(512, 1) fps_kernel(
    const float* __restrict__ coords, float* __restrict__ out_coords)
{
    extern __shared__ float4 sp[];     // Nq float4 = 128 KB (centroid fetch)
    __shared__ unsigned s_vb[2][16];   // double-buffered per-warp max bits
    __shared__ unsigned s_ib[2][16];   // double-buffered per-warp argmax idx

    const int b   = blockIdx.x;
    const int tid = threadIdx.x;
    const int w   = tid >> 5, lane = tid & 31;
    const float* cb = coords + (size_t)b * Nq * 3;

    for (int j = tid; j < Nq; j += 512)
        sp[j] = make_float4(cb[3 * j], cb[3 * j + 1], cb[3 * j + 2], 0.0f);
    __syncthreads();

    // pack 16 points (pair k = points 2k*512+tid, (2k+1)*512+tid) into regs
    u64p px[8], py[8], pz[8];
    float dist[16];
#pragma unroll
    for (int k = 0; k < 8; ++k) {
        const float4 a = sp[(2 * k) * 512 + tid];
        const float4 c = sp[(2 * k + 1) * 512 + tid];
        PK2(px[k], a.x, c.x);
        PK2(py[k], a.y, c.y);
        PK2(pz[k], a.z, c.z);
        dist[2 * k] = 3.0e38f; dist[2 * k + 1] = 3.0e38f;
    }

    int cur = 0;  // first sampled point is index 0 (reference init)
    float* ob = out_coords + (size_t)b * Mq * 3;

    for (int step = 0; step < Mq; ++step) {
        const int p = step & 1;
        const float4 c = sp[cur];
        if (tid == 0) {
            ob[3 * step + 0] = c.x;
            ob[3 * step + 1] = c.y;
            ob[3 * step + 2] = c.z;
        }
        u64p ncx, ncy, ncz;
        PK2(ncx, -c.x, -c.x);
        PK2(ncy, -c.y, -c.y);
        PK2(ncz, -c.z, -c.z);

#pragma unroll
        for (int k = 0; k < 8; ++k) {
            u64p dx, dy, dz, xx, yy, zz, ss, dd;
            ADD2(dx, px[k], ncx);
            ADD2(dy, py[k], ncy);
            ADD2(dz, pz[k], ncz);
            MUL2(xx, dx, dx);
            MUL2(yy, dy, dy);
            MUL2(zz, dz, dz);
            ADD2(ss, xx, yy);
            ADD2(dd, ss, zz);
            float d0, d1; UPK2(d0, d1, dd);
            dist[2 * k]     = fminf(dist[2 * k], d0);
            dist[2 * k + 1] = fminf(dist[2 * k + 1], d1);
        }
        // deferred tree-max + lowest-index equality scan (descending)
        float bv = dist[0];
#pragma unroll
        for (int i = 1; i < 16; ++i) bv = fmaxf(bv, dist[i]);
        int bi = 0;
#pragma unroll
        for (int i = 15; i >= 0; --i)
            if (dist[i] == bv) bi = i * 512 + tid;

        // stage1: warp argmax via redux (dist >= +0 -> bits monotone)
        const unsigned bb = __float_as_uint(bv);
        const unsigned wm = redux_max_u32(bb);
        const unsigned wbi =
            redux_min_u32((bb == wm) ? (unsigned)bi : 0x7fffffffu);
        if (lane == 0) { s_vb[p][w] = wm; s_ib[p][w] = wbi; }
        __syncthreads();

        // stage2: every warp redundantly reduces the 16 candidates
        const unsigned v2 = (lane < 16) ? s_vb[p][lane] : 0u;
        const unsigned i2 = (lane < 16) ? s_ib[p][lane] : 0x7fffffffu;
        const unsigned m2 = redux_max_u32(v2);
        cur = (int)redux_min_u32(
            (v2 == m2 && lane < 16) ? i2 : 0x7fffffffu);
    }
}

// ---------------------------------------------------------------------------
// kNN: thread-per-center, 128 threads/block, 16 blocks/batch (128 CTAs).
// Distance bit-identical to the passing R4/R5 kernels. Top-32 as a 32-node
// MAX-HEAP in SMEM keyed on u64 {idx | monotone(d2 bits)}:
//   - insert test: float d2 < root_f (== stable top_k insertion strict '<')
//   - eviction (heap root) = max value, ties -> max index (u64 max): exactly
//     the R4-passing eviction rule
//   - d2 + 0.0f canonicalizes -0 so bit ordering == float ordering
// Heap storage: 63 slots/thread (slots 32..62 are 0-sentinels so the 5-level
// sift-down can read children of every level-4 node without going OOB; a
// sentinel child, key 0, is < any real key -> sift stops). Stride 128 ->
// conflict-free. Insert = replace root + <=4-level sift-down.
// ---------------------------------------------------------------------------
#define HEAP_SLOTS 63

__global__ void __launch_bounds__(128, 1) knn_kernel(
    const float* __restrict__ coords, const float* __restrict__ out_coords)
{
    extern __shared__ char smraw[];
    ulonglong2* sA = (ulonglong2*)smraw;             // {x01, y01}   64 KB
    ulonglong2* sB = (ulonglong2*)(smraw + 65536);   // {z01, p01}   64 KB
    u64p*       hp = (u64p*)(smraw + 131072);        // heap 63x128  63 KB

    const int b   = blockIdx.y;
    const int tid = threadIdx.x;
    const float* cb = coords + (size_t)b * Nq * 3;

    for (int jp = tid; jp < Nq / 2; jp += 128) {
        const int j0 = 2 * jp, j1 = j0 + 1;
        const float x0 = cb[3 * j0], y0 = cb[3 * j0 + 1], z0 = cb[3 * j0 + 2];
        const float x1 = cb[3 * j1], y1 = cb[3 * j1 + 1], z1 = cb[3 * j1 + 2];
        const float p20 = __fadd_rn(
            __fadd_rn(__fmul_rn(x0, x0), __fmul_rn(y0, y0)), __fmul_rn(z0, z0));
        const float p21 = __fadd_rn(
            __fadd_rn(__fmul_rn(x1, x1), __fmul_rn(y1, y1)), __fmul_rn(z1, z1));
        ulonglong2 A, B;
        PK2(A.x, x0, x1); PK2(A.y, y0, y1);
        PK2(B.x, z0, z1); PK2(B.y, p20, p21);
        sA[jp] = A; sB[jp] = B;
    }
    // heap init: 32 real nodes decode to +inf (evicted first); slots 32..62
    // are 0-sentinels (key 0 < every real key since mono bits >= 0x80000000)
    const u64p INIT_KEY = 0xFF800000FFFFFFFFull;  // monotone(+inf) | idx-max
#pragma unroll
    for (int n = 0; n < 32; ++n) hp[n * 128 + tid] = INIT_KEY;
#pragma unroll
    for (int n = 32; n < HEAP_SLOTS; ++n) hp[n * 128 + tid] = 0ull;
    __syncthreads();

    const int m = blockIdx.x * 128 + tid;
    const float* cc = out_coords + ((size_t)b * Mq + m) * 3;
    const float cx = cc[0], cy = cc[1], cz = cc[2];
    const float c2 = __fadd_rn(
        __fadd_rn(__fmul_rn(cx, cx), __fmul_rn(cy, cy)), __fmul_rn(cz, cz));
    u64p vcx, vcy, vcz, vc2, vn2, vz0;
    PK2(vcx, cx, cx); PK2(vcy, cy, cy); PK2(vcz, cz, cz);
    PK2(vc2, c2, c2); PK2(vn2, -2.0f, -2.0f); PK2(vz0, 0.0f, 0.0f);

    u64p  root   = INIT_KEY;
    float root_f = __uint_as_float(0x7F800000u);   // +inf

    // insert: replace root, sift down (max child up), track new root + root_f
#define HEAP_INSERT(KEY)                                                    \
    {                                                                       \
        u64p key = (KEY);                                                   \
        u64p lc = hp[1 * 128 + tid], rc = hp[2 * 128 + tid];                \
        u64p mc = (rc > lc) ? rc : lc;                                      \
        if (mc > key) {                                                     \
            hp[0 * 128 + tid] = mc;                                         \
            root = mc;                                                      \
            int i = (rc > lc) ? 2 : 1;                                      \
            _Pragma("unroll")                                               \
            for (int lvl = 1; lvl < 5; ++lvl) {                             \
                const int cn = 2 * i + 1;                                   \
                lc = hp[cn * 128 + tid];                                    \
                rc = hp[(cn + 1) * 128 + tid];                              \
                mc = (rc > lc) ? rc : lc;                                   \
                if (mc <= key) break;                                       \
                hp[i * 128 + tid] = mc;                                     \
                i = (rc > lc) ? (cn + 1) : cn;                              \
            }                                                               \
            hp[i * 128 + tid] = key;                                        \
        } else {                                                            \
            hp[0 * 128 + tid] = key;                                        \
            root = key;                                                     \
        }                                                                   \
        const unsigned hi = (unsigned)(root >> 32);                         \
        const unsigned fb =                                                 \
            hi ^ ((hi & 0x80000000u) ? 0x80000000u : 0xFFFFFFFFu);          \
        root_f = __uint_as_float(fb);                                       \
    }

#define MONO(bits) ((bits) ^ ((unsigned)((int)(bits) >> 31) | 0x80000000u))

#pragma unroll 4
    for (int jp = 0; jp < Nq / 2; ++jp) {
        const ulonglong2 A = sA[jp];
        const ulonglong2 B = sB[jp];
        u64p t, dotv, s2, d2v;
        MUL2(t, A.x, vcx);
        FMA2(t, A.y, vcy, t);
        FMA2(dotv, B.x, vcz, t);
        ADD2(s2, vc2, B.y);
        FMA2(d2v, dotv, vn2, s2);
        ADD2(d2v, d2v, vz0);           // -0 -> +0 (value otherwise exact)
        float d0, d1; UPK2(d0, d1, d2v);
        if (d0 < root_f) {
            u64p k0; const unsigned m0 = MONO(__float_as_uint(d0));
            asm("mov.b64 %0, {%1, %2};" : "=l"(k0)
                : "r"((unsigned)(2 * jp)), "r"(m0));
            HEAP_INSERT(k0)
        }
        if (d1 < root_f) {
            u64p k1; const unsigned m1 = MONO(__float_as_uint(d1));
            asm("mov.b64 %0, {%1, %2};" : "=l"(k1)
                : "r"((unsigned)(2 * jp + 1)), "r"(m1));
            HEAP_INSERT(k1)
        }
    }
#undef HEAP_INSERT
#undef MONO

    int* ko = g_knn + ((size_t)b * Mq + m) * Kq;
#pragma unroll
    for (int s = 0; s < Kq; ++s)
        ko[s] = (int)(unsigned)(hp[s * 128 + tid] & 0xFFFFFFFFull);
}

// ---------------------------------------------------------------------------
// Aggregation: 4 centers per 128-thread block; each thread owns 4 channels
// (float4); mean = sum * (1/32).
// ---------------------------------------------------------------------------
__global__ void __launch_bounds__(128, 1) agg_kernel(
    const float* __restrict__ feats, float* __restrict__ out_feats)
{
    const int slot = threadIdx.x >> 5;   // center slot in block (0..3)
    const int lane = threadIdx.x & 31;   // channel quad (0..31) -> 128 ch
    const int bm   = blockIdx.x * 4 + slot;
    const int b    = bm >> 11;           // / Mq

    __shared__ int nb[4][Kq];
    nb[slot][lane] = g_knn[(size_t)bm * Kq + lane];
    __syncwarp();

    const float4* fb = (const float4*)(feats + (size_t)b * Nq * Cq);
    float ax = 0.f, ay = 0.f, az = 0.f, aw = 0.f;
#pragma unroll
    for (int s = 0; s < Kq; ++s) {
        const float4 v = fb[(size_t)nb[slot][s] * 32 + lane];
        ax += v.x; ay += v.y; az += v.z; aw += v.w;
    }
    float4 r;
    r.x = ax * 0.03125f; r.y = ay * 0.03125f;
    r.z = az * 0.03125f; r.w = aw * 0.03125f;
    ((float4*)out_feats)[(size_t)bm * 32 + lane] = r;
}

// ---------------------------------------------------------------------------
extern "C" void kernel_launch(void* const* d_in, const int* in_sizes, int n_in,
                              void* d_out, int out_size)
{
    const float* coords = (const float*)d_in[0];  // (8, 8192, 3) f32
    const float* feats  = (const float*)d_in[1];  // (8, 8192, 128) f32
    float* out        = (float*)d_out;
    float* out_coords = out;                       // (8, 2048, 3)
    float* out_feats  = out + (size_t)Bq * Mq * 3; // (8, 2048, 128)

    const int knn_smem = 131072 + HEAP_SLOTS * 128 * 8;  // 195,584 B

    cudaFuncSetAttribute(fps_kernel, cudaFuncAttributeMaxDynamicSharedMemorySize,
                         Nq * (int)sizeof(float4));
    cudaFuncSetAttribute(knn_kernel, cudaFuncAttributeMaxDynamicSharedMemorySize,
                         knn_smem);

    fps_kernel<<<Bq, 512, Nq * sizeof(float4)>>>(coords, out_coords);
    knn_kernel<<<dim3(Mq / 128, Bq), 128, knn_smem>>>(coords, out_coords);
    agg_kernel<<<Bq * Mq / 4, 128>>>(feats, out_feats);
}

// round 9
// speedup vs baseline: 2.1344x; 1.1522x over previous
#include <cuda_runtime.h>

#define Bq 8
#define Nq 8192
#define Cq 128
#define Mq 2048
#define Kq 32

typedef unsigned long long u64p;

// device-global scratch (allocation-free)
__device__ ulonglong2 g_pA[Bq * (Nq / 2)];   // packed {x01, y01} per pair
__device__ ulonglong2 g_pB[Bq * (Nq / 2)];   // packed {z01, p2_01} per pair
__device__ unsigned   g_prog[Bq];            // FPS progress counters

// ---- packed f32x2 helpers (per-lane rounding identical to scalar RN ops) ----
#define PK2(d, lo, hi)                                                      \
    asm("mov.b64 %0, {%1, %2};" : "=l"(d)                                   \
        : "r"(__float_as_uint(lo)), "r"(__float_as_uint(hi)))
#define UPK2(lo, hi, s)                                                     \
    do { unsigned _a, _b;                                                   \
         asm("mov.b64 {%0, %1}, %2;" : "=r"(_a), "=r"(_b) : "l"(s));        \
         (lo) = __uint_as_float(_a); (hi) = __uint_as_float(_b); } while (0)
#define ADD2(d, a, b) asm("add.rn.f32x2 %0, %1, %2;" : "=l"(d) : "l"(a), "l"(b))
#define MUL2(d, a, b) asm("mul.rn.f32x2 %0, %1, %2;" : "=l"(d) : "l"(a), "l"(b))
#define FMA2(d, a, b, c)                                                    \
    asm("fma.rn.f32x2 %0, %1, %2, %3;" : "=l"(d) : "l"(a), "l"(b), "l"(c))

__device__ __forceinline__ unsigned redux_max_u32(unsigned v) {
    unsigned r;
    asm("redux.sync.max.u32 %0, %1, 0xffffffff;" : "=r"(r) : "r"(v));
    return r;
}
__device__ __forceinline__ unsigned redux_min_u32(unsigned v) {
    unsigned r;
    asm("redux.sync.min.u32 %0, %1, 0xffffffff;" : "=r"(r) : "r"(v));
    return r;
}

// ---------------------------------------------------------------------------
// pack kernel: SoA pair-packed coords + |p|^2 (bit-exact p2 path), and
// resets the progress counters (needed on every graph replay).
// ---------------------------------------------------------------------------
__global__ void __launch_bounds__(512, 1) pack_kernel(
    const float* __restrict__ coords)
{
    const int b   = blockIdx.x;
    const int tid = threadIdx.x;
    if (tid == 0) g_prog[b] = 0u;
    const float* cb = coords + (size_t)b * Nq * 3;
    for (int jp = tid; jp < Nq / 2; jp += 512) {
        const int j0 = 2 * jp, j1 = j0 + 1;
        const float x0 = cb[3 * j0], y0 = cb[3 * j0 + 1], z0 = cb[3 * j0 + 2];
        const float x1 = cb[3 * j1], y1 = cb[3 * j1 + 1], z1 = cb[3 * j1 + 2];
        const float p20 = __fadd_rn(
            __fadd_rn(__fmul_rn(x0, x0), __fmul_rn(y0, y0)), __fmul_rn(z0, z0));
        const float p21 = __fadd_rn(
            __fadd_rn(__fmul_rn(x1, x1), __fmul_rn(y1, y1)), __fmul_rn(z1, z1));
        ulonglong2 A, B;
        PK2(A.x, x0, x1); PK2(A.y, y0, y1);
        PK2(B.x, z0, z1); PK2(B.y, p20, p21);
        g_pA[b * (Nq / 2) + jp] = A;
        g_pB[b * (Nq / 2) + jp] = B;
    }
}

// ---------------------------------------------------------------------------
// Fused kernel. blockIdx 0..7: FPS producer (bit-exact R7 code + release
// stores of progress). blockIdx 8..135: kNN consumer — 4-way point-split
// scan + exact u64-key merge + fused feature aggregation.
// All 136 CTAs are co-resident (1/SM), so spin-waiting cannot deadlock.
// ---------------------------------------------------------------------------
#define HSTRIDE 512     // heap column stride (one column per thread)

// hygienic heap insert: replace root, sift down (max child up), update root.
// All internal names are reserved (_hs_*) so call-site argument names can
// never be shadowed (the R8 merge bug: `HEAP_SIFT(key)` self-initialized).
#define HEAP_SIFT(KEY)                                                      \
    {                                                                       \
        const u64p _hs_k = (KEY);                                           \
        u64p _hs_lc = hp[1 * HSTRIDE + tid];                                \
        u64p _hs_rc = hp[2 * HSTRIDE + tid];                                \
        u64p _hs_mc = (_hs_rc > _hs_lc) ? _hs_rc : _hs_lc;                  \
        if (_hs_mc > _hs_k) {                                               \
            hp[0 * HSTRIDE + tid] = _hs_mc;                                 \
            root = _hs_mc;                                                  \
            int _hs_i = (_hs_rc > _hs_lc) ? 2 : 1;                          \
            _Pragma("unroll")                                               \
            for (int _hs_lvl = 1; _hs_lvl < 5; ++_hs_lvl) {                 \
                const int _hs_cn = 2 * _hs_i + 1;                           \
                if (_hs_cn > 31) break;                                     \
                _hs_lc = hp[_hs_cn * HSTRIDE + tid];                        \
                _hs_rc = hp[(_hs_cn + 1) * HSTRIDE + tid];                  \
                _hs_mc = (_hs_rc > _hs_lc) ? _hs_rc : _hs_lc;               \
                if (_hs_mc <= _hs_k) break;                                 \
                hp[_hs_i * HSTRIDE + tid] = _hs_mc;                         \
                _hs_i = (_hs_rc > _hs_lc) ? (_hs_cn + 1) : _hs_cn;          \
            }                                                               \
            hp[_hs_i * HSTRIDE + tid] = _hs_k;                              \
        } else {                                                            \
            hp[0 * HSTRIDE + tid] = _hs_k;                                  \
            root = _hs_k;                                                   \
        }                                                                   \
    }
#define ROOTF_UPDATE()                                                      \
    {                                                                       \
        const unsigned _ru_hi = (unsigned)(root >> 32);                     \
        const unsigned _ru_fb =                                             \
            _ru_hi ^ ((_ru_hi & 0x80000000u) ? 0x80000000u : 0xFFFFFFFFu);  \
        root_f = __uint_as_float(_ru_fb);                                   \
    }
#define MONO(bits) ((bits) ^ ((unsigned)((int)(bits) >> 31) | 0x80000000u))

__global__ void __launch_bounds__(512, 1) fused_kernel(
    const float* __restrict__ coords, const float* __restrict__ feats,
    float* __restrict__ out_coords, float* __restrict__ out_feats)
{
    extern __shared__ char smraw[];
    const int tid = threadIdx.x;

    if (blockIdx.x < Bq) {
        // =================== FPS role (unchanged from R7) ===================
        float4* sp = (float4*)smraw;       // Nq float4 = 128 KB
        __shared__ unsigned s_vb[2][16];
        __shared__ unsigned s_ib[2][16];

        const int b    = blockIdx.x;
        const int w    = tid >> 5, lane = tid & 31;
        const float* cb = coords + (size_t)b * Nq * 3;

        for (int j = tid; j < Nq; j += 512)
            sp[j] = make_float4(cb[3 * j], cb[3 * j + 1], cb[3 * j + 2], 0.0f);
        __syncthreads();

        u64p px[8], py[8], pz[8];
        float dist[16];
#pragma unroll
        for (int k = 0; k < 8; ++k) {
            const float4 a = sp[(2 * k) * 512 + tid];
            const float4 c = sp[(2 * k + 1) * 512 + tid];
            PK2(px[k], a.x, c.x);
            PK2(py[k], a.y, c.y);
            PK2(pz[k], a.z, c.z);
            dist[2 * k] = 3.0e38f; dist[2 * k + 1] = 3.0e38f;
        }

        int cur = 0;
        float* ob = out_coords + (size_t)b * Mq * 3;

        for (int step = 0; step < Mq; ++step) {
            const int p = step & 1;
            const float4 c = sp[cur];
            if (tid == 0) {
                ob[3 * step + 0] = c.x;
                ob[3 * step + 1] = c.y;
                ob[3 * step + 2] = c.z;
                if ((step & 63) == 63) {  // steps 0..step now final
                    asm volatile("st.release.gpu.global.u32 [%0], %1;"
                                 :: "l"(&g_prog[b]), "r"((unsigned)(step + 1))
                                 : "memory");
                }
            }
            u64p ncx, ncy, ncz;
            PK2(ncx, -c.x, -c.x);
            PK2(ncy, -c.y, -c.y);
            PK2(ncz, -c.z, -c.z);

#pragma unroll
            for (int k = 0; k < 8; ++k) {
                u64p dx, dy, dz, xx, yy, zz, ss, dd;
                ADD2(dx, px[k], ncx);
                ADD2(dy, py[k], ncy);
                ADD2(dz, pz[k], ncz);
                MUL2(xx, dx, dx);
                MUL2(yy, dy, dy);
                MUL2(zz, dz, dz);
                ADD2(ss, xx, yy);
                ADD2(dd, ss, zz);
                float d0, d1; UPK2(d0, d1, dd);
                dist[2 * k]     = fminf(dist[2 * k], d0);
                dist[2 * k + 1] = fminf(dist[2 * k + 1], d1);
            }
            float bv = dist[0];
#pragma unroll
            for (int i = 1; i < 16; ++i) bv = fmaxf(bv, dist[i]);
            int bi = 0;
#pragma unroll
            for (int i = 15; i >= 0; --i)
                if (dist[i] == bv) bi = i * 512 + tid;

            const unsigned bb = __float_as_uint(bv);
            const unsigned wm = redux_max_u32(bb);
            const unsigned wbi =
                redux_min_u32((bb == wm) ? (unsigned)bi : 0x7fffffffu);
            if (lane == 0) { s_vb[p][w] = wm; s_ib[p][w] = wbi; }
            __syncthreads();

            const unsigned v2 = (lane < 16) ? s_vb[p][lane] : 0u;
            const unsigned i2 = (lane < 16) ? s_ib[p][lane] : 0x7fffffffu;
            const unsigned m2 = redux_max_u32(v2);
            cur = (int)redux_min_u32(
                (v2 == m2 && lane < 16) ? i2 : 0x7fffffffu);
        }
        // final release so consumers of the last block always proceed
        if (tid == 0)
            asm volatile("st.release.gpu.global.u32 [%0], %1;"
                         :: "l"(&g_prog[b]), "r"((unsigned)Mq) : "memory");
        return;
    }

    // ======================= kNN + aggregation role =======================
    u64p* hp = (u64p*)smraw;               // 33 x 512 u64 = 132 KB
    const int cta = blockIdx.x - Bq;
    const int b   = cta >> 4;              // batch
    const int xl  = cta & 15;              // center block within batch
    const int t   = tid & 127;             // center slot (0..127)
    const int g   = tid >> 7;              // point quarter (0..3)
    const int m   = xl * 128 + t;          // center index within batch

    // heap init: 32 real nodes -> +inf keys; slot 32 = 0-sentinel
    const u64p INIT_KEY = 0xFF800000FFFFFFFFull;
#pragma unroll
    for (int n = 0; n < 32; ++n) hp[n * HSTRIDE + tid] = INIT_KEY;
    hp[32 * HSTRIDE + tid] = 0ull;
    __syncthreads();

    // wait for FPS progress (centers [0, (xl+1)*128) final)
    const unsigned need = (unsigned)((xl + 1) * 128);
    if (tid == 0) {
        unsigned v;
        do {
            asm volatile("ld.acquire.gpu.global.u32 %0, [%1];"
                         : "=r"(v) : "l"(&g_prog[b]) : "memory");
            if (v >= need) break;
            __nanosleep(256);
        } while (true);
    }
    __syncthreads();
    {   // per-thread acquire (counter is monotone -> sees >= need)
        unsigned v;
        asm volatile("ld.acquire.gpu.global.u32 %0, [%1];"
                     : "=r"(v) : "l"(&g_prog[b]) : "memory");
        (void)v;
    }

    const float* cc = out_coords + ((size_t)b * Mq + m) * 3;
    const float cx = cc[0], cy = cc[1], cz = cc[2];
    const float c2 = __fadd_rn(
        __fadd_rn(__fmul_rn(cx, cx), __fmul_rn(cy, cy)), __fmul_rn(cz, cz));
    u64p vcx, vcy, vcz, vc2, vn2, vz0;
    PK2(vcx, cx, cx); PK2(vcy, cy, cy); PK2(vcz, cz, cz);
    PK2(vc2, c2, c2); PK2(vn2, -2.0f, -2.0f); PK2(vz0, 0.0f, 0.0f);

    u64p  root   = INIT_KEY;
    float root_f = __uint_as_float(0x7F800000u);   // +inf

    // scan this quarter of the points (distance math bit-exact vs R7)
    const ulonglong2* pA = g_pA + (size_t)b * (Nq / 2);
    const ulonglong2* pB = g_pB + (size_t)b * (Nq / 2);
    const int jp0 = g * (Nq / 8), jp1 = jp0 + (Nq / 8);
#pragma unroll 4
    for (int jp = jp0; jp < jp1; ++jp) {
        const ulonglong2 A = pA[jp];
        const ulonglong2 B = pB[jp];
        u64p tt, dotv, s2, d2v;
        MUL2(tt, A.x, vcx);
        FMA2(tt, A.y, vcy, tt);
        FMA2(dotv, B.x, vcz, tt);
        ADD2(s2, vc2, B.y);
        FMA2(d2v, dotv, vn2, s2);
        ADD2(d2v, d2v, vz0);           // -0 -> +0 (value otherwise exact)
        float d0, d1; UPK2(d0, d1, d2v);
        if (d0 < root_f) {
            u64p k0; const unsigned m0 = MONO(__float_as_uint(d0));
            asm("mov.b64 %0, {%1, %2};" : "=l"(k0)
                : "r"((unsigned)(2 * jp)), "r"(m0));
            HEAP_SIFT(k0) ROOTF_UPDATE()
        }
        if (d1 < root_f) {
            u64p k1; const unsigned m1 = MONO(__float_as_uint(d1));
            asm("mov.b64 %0, {%1, %2};" : "=l"(k1)
                : "r"((unsigned)(2 * jp + 1)), "r"(m1));
            HEAP_SIFT(k1) ROOTF_UPDATE()
        }
    }
    __syncthreads();

    // merge: thread t (<128) folds the 3 foreign partial heaps into its own.
    // u64 key order == (value, index) stable rule; 32 smallest of the union
    // == exact global stable top-32.
    if (tid < 128) {
#pragma unroll
        for (int g2 = 1; g2 < 4; ++g2) {
            const int col = t + 128 * g2;
#pragma unroll
            for (int n = 0; n < 32; ++n) {
                const u64p fkey = hp[n * HSTRIDE + col];
                if (fkey < root) HEAP_SIFT(fkey)
            }
        }
    }
    __syncthreads();

    // fused aggregation: warp w handles centers w*8..w*8+7; lane = channel
    // quad. Neighbor indices read from heap slot low words (ascending slots).
    const int w    = tid >> 5, lane = tid & 31;
    const unsigned* hlo = (const unsigned*)hp;   // low word of each u64 slot
    const float4* fb4 = (const float4*)(feats + (size_t)b * Nq * Cq);
#pragma unroll
    for (int c8 = 0; c8 < 8; ++c8) {
        const int c  = w * 8 + c8;               // center slot 0..127
        const int mm = xl * 128 + c;
        float ax = 0.f, ay = 0.f, az = 0.f, aw = 0.f;
#pragma unroll
        for (int s = 0; s < Kq; ++s) {
            const unsigned idx = hlo[(s * HSTRIDE + c) * 2];
            const float4 v = fb4[(size_t)idx * 32 + lane];
            ax += v.x; ay += v.y; az += v.z; aw += v.w;
        }
        float4 r;
        r.x = ax * 0.03125f; r.y = ay * 0.03125f;
        r.z = az * 0.03125f; r.w = aw * 0.03125f;
        ((float4*)out_feats)[((size_t)b * Mq + mm) * 32 + lane] = r;
    }
}

// ---------------------------------------------------------------------------
extern "C" void kernel_launch(void* const* d_in, const int* in_sizes, int n_in,
                              void* d_out, int out_size)
{
    const float* coords = (const float*)d_in[0];  // (8, 8192, 3) f32
    const float* feats  = (const float*)d_in[1];  // (8, 8192, 128) f32
    float* out        = (float*)d_out;
    float* out_coords = out;                       // (8, 2048, 3)
    float* out_feats  = out + (size_t)Bq * Mq * 3; // (8, 2048, 128)

    const int fused_smem = 33 * HSTRIDE * 8;       // 135,168 B (>= 128 KB FPS)

    cudaFuncSetAttribute(fused_kernel, cudaFuncAttributeMaxDynamicSharedMemorySize,
                         fused_smem);

    pack_kernel<<<Bq, 512>>>(coords);
    fused_kernel<<<Bq + Bq * 16, 512, fused_smem>>>(coords, feats,
                                                    out_coords, out_feats);
}